// round 14
// baseline (speedup 1.0000x reference)
#include <cuda_runtime.h>
#include <cuda_fp16.h>
#include <math.h>
#include <stdint.h>

// Problem constants
#define FEAT_DIM 512
#define H_DIM    512
#define DEPTH    17
#define N_NODES  ((1 << DEPTH) - 1)   // 131071
#define GATE5    (5 * H_DIM)          // 2560
#define GXS      3072                 // combined row stride: 2560 iofu r + 512 px
#define MAX_PREV (1 << (DEPTH - 2))   // 32768

// ---------------------------------------------------------------------------
// Scratch (static __device__ allocations)
// ---------------------------------------------------------------------------
__device__ __half g_gx   [(size_t)N_NODES * GXS];      // 805 MB combined iofux|px
__device__ float  g_c    [(size_t)N_NODES * H_DIM];    // 268 MB (fp32 recurrence)
__device__ __half g_hh   [(size_t)MAX_PREV * GATE5];   // 168 MB
__device__ __half g_feat16[(size_t)N_NODES * FEAT_DIM];// 134 MB
__device__ __half g_h16   [(size_t)N_NODES * H_DIM];   // 134 MB
__device__ __half g_w_cat [GXS * FEAT_DIM];            // rows 0..2559 iofux, 2560..3071 px
__device__ __half g_w_iofuh[GATE5 * H_DIM];

__device__ __forceinline__ uint32_t smem_u32(const void* p) {
    uint32_t a;
    asm("{ .reg .u64 t; cvta.to.shared.u64 t, %1; cvt.u32.u64 %0, t; }" : "=r"(a) : "l"(p));
    return a;
}
__device__ __forceinline__ uint32_t pack2h(float lo, float hi) {
    __half2 h = __floats2half2_rn(lo, hi);
    return *(uint32_t*)&h;
}

// ---------------------------------------------------------------------------
// fp32 -> fp16 conversion, 4 float4 per thread
// ---------------------------------------------------------------------------
__global__ void __launch_bounds__(256) f2h_kernel(
    const float* __restrict__ in, __half* __restrict__ out, int n4)
{
    int i0 = blockIdx.x * 1024 + threadIdx.x;
#pragma unroll
    for (int u = 0; u < 4; u++) {
        int i = i0 + u * 256;
        if (i < n4) {
            float4 v = ((const float4*)in)[i];
            ((uint2*)out)[i] = make_uint2(pack2h(v.x, v.y), pack2h(v.z, v.w));
        }
    }
}

// ---------------------------------------------------------------------------
// fp16-in fp16-out mma GEMM, cp.async 4-stage ring, one barrier per stage.
// C[M,N] = A[M,K] @ B[N,K]^T. Block 128x256, 512 thr = 16 warps (4x4),
// warp tile 32x64 (validated fragment/epilogue mapping), fp32 accum.
// ---------------------------------------------------------------------------
#define BM 128
#define BN 256
#define BK 32
#define LH 40
#define A_BUF (BM * LH * 2)            // 10240 bytes
#define B_BUF (BN * LH * 2)            // 20480 bytes
#define STAGE_B (A_BUF + B_BUF)        // 30720
#define NSTAGE 4
#define SMEM_GEMM (NSTAGE * STAGE_B)   // 122880

__device__ __forceinline__ void mma_f16(float c[4],
                                        uint32_t a0, uint32_t a1, uint32_t a2, uint32_t a3,
                                        uint32_t b0, uint32_t b1)
{
    asm volatile(
        "mma.sync.aligned.m16n8k16.row.col.f32.f16.f16.f32 "
        "{%0,%1,%2,%3}, {%4,%5,%6,%7}, {%8,%9}, {%0,%1,%2,%3};\n"
        : "+f"(c[0]), "+f"(c[1]), "+f"(c[2]), "+f"(c[3])
        : "r"(a0), "r"(a1), "r"(a2), "r"(a3), "r"(b0), "r"(b1));
}
#define LDSM_X4(r0, r1, r2, r3, addr) \
    asm volatile("ldmatrix.sync.aligned.m8n8.x4.shared.b16 {%0,%1,%2,%3}, [%4];" \
                 : "=r"(r0), "=r"(r1), "=r"(r2), "=r"(r3) : "r"(addr))
#define CP_ASYNC16(dst, src) \
    asm volatile("cp.async.cg.shared.global [%0], [%1], 16;" :: "r"(dst), "l"(src) : "memory")
#define CP_COMMIT() asm volatile("cp.async.commit_group;" ::: "memory")
#define CP_WAIT2()  asm volatile("cp.async.wait_group 2;" ::: "memory")

__global__ void __launch_bounds__(512, 1) h16gemm_tn(
    const __half* __restrict__ A, const __half* __restrict__ B,
    __half* __restrict__ C, int M, int N, int K)
{
    extern __shared__ __align__(16) char sm[];
    const uint32_t sb = smem_u32(sm);

    const int tid  = threadIdx.x;
    const int lane = tid & 31;
    const int wid  = tid >> 5;       // 0..15
    const int wm   = wid & 3;        // warp row group (32 rows)
    const int wn   = wid >> 2;       // warp col group (64 cols), 0..3
    const int gid  = lane >> 2;
    const int tig  = lane & 3;
    const int bm   = blockIdx.y * BM;
    const int bn   = blockIdx.x * BN;

    // Loaders: tid<256 -> A rows (2 x 16B); tid>=256 -> B rows (4 x 16B)
    const bool isA  = tid < 256;
    const int  lrow = isA ? (tid >> 1) : (tid - 256);   // A: 0..127, B: 0..255
    const int  loff = isA ? ((tid & 1) * 32) : 0;

    int ar = bm + lrow; if (ar >= M) ar = M - 1;
    const char* srcB;
    uint32_t dst0;
    if (isA) {
        srcB = (const char*)(A + (size_t)ar * K) + loff;
        dst0 = sb + lrow * 80 + loff;
    } else {
        srcB = (const char*)(B + (size_t)(bn + lrow) * K);
        dst0 = sb + A_BUF + lrow * 80;
    }

    // ldmatrix lane addresses (stage 0 base)
    uint32_t aAdr[2];
#pragma unroll
    for (int mt = 0; mt < 2; mt++) {
        int m0 = wm * 32 + mt * 16;
        aAdr[mt] = sb + (((m0 + (lane & 15)) * LH) + (lane >> 4) * 8) * 2;
    }
    uint32_t bAdr[4];
#pragma unroll
    for (int p = 0; p < 4; p++) {
        int n0 = wn * 64 + p * 16 + ((lane >> 4) << 3) + (lane & 7);
        bAdr[p] = sb + A_BUF + (n0 * LH + (lane & 8)) * 2;
    }

    float acc[2][8][4];
#pragma unroll
    for (int mt = 0; mt < 2; mt++)
#pragma unroll
        for (int nt = 0; nt < 8; nt++)
#pragma unroll
            for (int r = 0; r < 4; r++) acc[mt][nt][r] = 0.f;

    auto issue = [&](int s) {
        const uint32_t so = (uint32_t)(s % NSTAGE) * STAGE_B;
        const int kb = s * BK * 2;           // byte offset along K
        if (isA) {
            CP_ASYNC16(dst0 + so,      srcB + kb);
            CP_ASYNC16(dst0 + so + 16, srcB + kb + 16);
        } else {
            CP_ASYNC16(dst0 + so,      srcB + kb);
            CP_ASYNC16(dst0 + so + 16, srcB + kb + 16);
            CP_ASYNC16(dst0 + so + 32, srcB + kb + 32);
            CP_ASYNC16(dst0 + so + 48, srcB + kb + 48);
        }
        CP_COMMIT();
    };

    const int nst = K / BK;
    issue(0);
    issue(1);

    for (int s = 0; s < nst; s++) {
        // Writer buffer (s+2)%4; concurrent readers are at stage s-1 -> (s-1)%4. Disjoint.
        if (s + 2 < nst) issue(s + 2);
        else             CP_COMMIT();
        CP_WAIT2();
        __syncthreads();

        const uint32_t so = (uint32_t)(s % NSTAGE) * STAGE_B;
#pragma unroll
        for (int ks = 0; ks < 2; ks++) {
            const uint32_t ko = so + ks * 32;
            uint32_t af[2][4];
#pragma unroll
            for (int mt = 0; mt < 2; mt++)
                LDSM_X4(af[mt][0], af[mt][1], af[mt][2], af[mt][3], aAdr[mt] + ko);
            uint32_t bf[8][2];
#pragma unroll
            for (int p = 0; p < 4; p++)
                LDSM_X4(bf[2*p][0], bf[2*p][1], bf[2*p+1][0], bf[2*p+1][1], bAdr[p] + ko);
#pragma unroll
            for (int mt = 0; mt < 2; mt++)
#pragma unroll
                for (int nt = 0; nt < 8; nt++)
                    mma_f16(acc[mt][nt], af[mt][0], af[mt][1], af[mt][2], af[mt][3],
                            bf[nt][0], bf[nt][1]);
        }
    }

#pragma unroll
    for (int mt = 0; mt < 2; mt++) {
        int r0 = bm + wm * 32 + mt * 16 + gid;
        int r1 = r0 + 8;
#pragma unroll
        for (int nt = 0; nt < 8; nt++) {
            int col = bn + wn * 64 + nt * 8 + tig * 2;
            if (r0 < M)
                *(__half2*)(C + (size_t)r0 * N + col) = __floats2half2_rn(acc[mt][nt][0], acc[mt][nt][1]);
            if (r1 < M)
                *(__half2*)(C + (size_t)r1 * N + col) = __floats2half2_rn(acc[mt][nt][2], acc[mt][nt][3]);
        }
    }
}

// ---------------------------------------------------------------------------
// Small-M fp32 GEMM (fp16 out): 16 cols/block x 16 lanes/col, shfl reduce.
// ---------------------------------------------------------------------------
__global__ void __launch_bounds__(256) small_gemm_tn(
    const float* __restrict__ A, const float* __restrict__ B,
    __half* __restrict__ C, int N, int K)
{
    __shared__ float Arow[FEAT_DIM];
    const int tid  = threadIdx.x;
    const int lane = tid & 31;
    const int wid  = tid >> 5;
    const int m    = blockIdx.y;

    if (tid < FEAT_DIM / 4)
        ((float4*)Arow)[tid] = ((const float4*)(A + (size_t)m * K))[tid];
    __syncthreads();

    const int col = blockIdx.x * 16 + wid * 2 + (lane >> 4);
    const int hl  = lane & 15;

    const float4* Br = (const float4*)(B + (size_t)col * K) + hl;
    const float4* Ar = (const float4*)Arow + hl;
    float s = 0.f;
#pragma unroll
    for (int i = 0; i < 8; i++) {
        float4 b = Br[i * 16];
        float4 a = Ar[i * 16];
        s += a.x * b.x + a.y * b.y + a.z * b.z + a.w * b.w;
    }
#pragma unroll
    for (int off = 8; off >= 1; off >>= 1)
        s += __shfl_xor_sync(0xffffffff, s, off);
    if (hl == 0)
        C[(size_t)m * N + col] = __float2half_rn(s);
}

// ---------------------------------------------------------------------------
// Per-level fused gates: combined gx (iofu r | px) fp16 in, fp32 out (+ h16)
// ---------------------------------------------------------------------------
__device__ __forceinline__ float sigf(float x) { return 1.f / (1.f + expf(-x)); }
__device__ __forceinline__ float4 f4add(float4 a, float4 b) {
    return make_float4(a.x + b.x, a.y + b.y, a.z + b.z, a.w + b.w);
}
__device__ __forceinline__ float4 loadh4(const __half* p) {
    __half2 a = *(const __half2*)p;
    __half2 b = *(const __half2*)(p + 2);
    float2 fa = __half22float2(a), fb = __half22float2(b);
    return make_float4(fa.x, fa.y, fb.x, fb.y);
}

__global__ void __launch_bounds__(256) lstm_level_kernel(
    const float* __restrict__ iofux_b, const float* __restrict__ iofuh_b,
    const float* __restrict__ px_b, float* __restrict__ out,
    int start, int n, int hasPrev, int writeH16)
{
    int idx = blockIdx.x * 256 + threadIdx.x;
    int total = n * (H_DIM / 4);
    if (idx >= total) return;

    int j  = idx >> 7;
    int t4 = idx & 127;
    size_t g = (size_t)start + j;

    const __half* gx = g_gx + g * GXS + t4 * 4;
    float4 vi = loadh4(gx);
    float4 vo = loadh4(gx + 512);
    float4 vf = loadh4(gx + 1024);
    float4 vu = loadh4(gx + 1536);
    float4 vr = loadh4(gx + 2048);

    float4 pc = make_float4(0.f, 0.f, 0.f, 0.f);
    if (hasPrev) {
        const __half* gh = g_hh + (size_t)(j >> 1) * GATE5 + t4 * 4;
        vi = f4add(vi, loadh4(gh));
        vo = f4add(vo, loadh4(gh + 512));
        vf = f4add(vf, loadh4(gh + 1024));
        vu = f4add(vu, loadh4(gh + 1536));
        vr = f4add(vr, loadh4(gh + 2048));
        size_t parent = (g - 1) >> 1;
        pc = ((const float4*)g_c)[parent * 128 + t4];
    }

    const float4* bx = (const float4*)iofux_b;
    const float4* bh = (const float4*)iofuh_b;
    vi = f4add(vi, f4add(bx[t4],       bh[t4]));
    vo = f4add(vo, f4add(bx[128 + t4], bh[128 + t4]));
    vf = f4add(vf, f4add(bx[256 + t4], bh[256 + t4]));
    vu = f4add(vu, f4add(bx[384 + t4], bh[384 + t4]));
    vr = f4add(vr, f4add(bx[512 + t4], bh[512 + t4]));

    float4 px4 = f4add(loadh4(gx + 2560), ((const float4*)px_b)[t4]);

    float4 c4, h4;
#define GATE(C) {                                                     \
        float i_ = sigf(vi.C); float o_ = sigf(vo.C);                 \
        float f_ = sigf(vf.C); float u_ = tanhf(vu.C);                \
        float r_ = sigf(vr.C);                                        \
        float c_ = i_ * u_ + f_ * pc.C;                               \
        float h_ = o_ * tanhf(c_);                                    \
        c4.C = c_; h4.C = r_ * h_ + (1.f - r_) * px4.C; }
    GATE(x) GATE(y) GATE(z) GATE(w)
#undef GATE

    ((float4*)g_c)[g * 128 + t4] = c4;
    ((float4*)out)[g * 128 + t4] = h4;
    if (writeH16)
        *(uint2*)(g_h16 + g * H_DIM + t4 * 4) =
            make_uint2(pack2h(h4.x, h4.y), pack2h(h4.z, h4.w));
}

// ---------------------------------------------------------------------------
// kernel_launch: conversions -> fork (per-level GEMM chunks on s2) -> join
// ---------------------------------------------------------------------------
extern "C" void kernel_launch(void* const* d_in, const int* in_sizes, int n_in,
                              void* d_out, int out_size)
{
    const float* features = (const float*)d_in[0];
    const float* px_w     = (const float*)d_in[1];
    const float* px_b     = (const float*)d_in[2];
    const float* iofux_w  = (const float*)d_in[3];
    const float* iofux_b  = (const float*)d_in[4];
    const float* iofuh_w  = (const float*)d_in[5];
    const float* iofuh_b  = (const float*)d_in[6];
    float* out = (float*)d_out;

    __half *gx_p, *hh_p, *feat16, *h16, *w_cat, *w_iofuh;
    cudaGetSymbolAddress((void**)&gx_p,    g_gx);
    cudaGetSymbolAddress((void**)&hh_p,    g_hh);
    cudaGetSymbolAddress((void**)&feat16,  g_feat16);
    cudaGetSymbolAddress((void**)&h16,     g_h16);
    cudaGetSymbolAddress((void**)&w_cat,   g_w_cat);
    cudaGetSymbolAddress((void**)&w_iofuh, g_w_iofuh);

    static cudaStream_t s2 = nullptr;
    static cudaEvent_t evConv = nullptr;
    static cudaEvent_t evChunk[7];
    if (!s2) {
        cudaStreamCreateWithFlags(&s2, cudaStreamNonBlocking);
        cudaEventCreateWithFlags(&evConv, cudaEventDisableTiming);
        for (int i = 0; i < 7; i++)
            cudaEventCreateWithFlags(&evChunk[i], cudaEventDisableTiming);
        cudaFuncSetAttribute(h16gemm_tn, cudaFuncAttributeMaxDynamicSharedMemorySize, SMEM_GEMM);
    }

    dim3 blk(256);
    dim3 gblk(512);

    // fp32 -> fp16 conversions (main stream)
    {
        int n4 = (N_NODES * FEAT_DIM) / 4;
        f2h_kernel<<<(n4 + 1023) / 1024, blk>>>(features, feat16, n4);
        n4 = (GATE5 * FEAT_DIM) / 4;
        f2h_kernel<<<(n4 + 1023) / 1024, blk>>>(iofux_w, w_cat, n4);
        n4 = (H_DIM * FEAT_DIM) / 4;
        f2h_kernel<<<(n4 + 1023) / 1024, blk>>>(px_w, w_cat + (size_t)GATE5 * FEAT_DIM, n4);
        n4 = (GATE5 * H_DIM) / 4;
        f2h_kernel<<<(n4 + 1023) / 1024, blk>>>(iofuh_w, w_iofuh, n4);
    }

    // Fork: per-level-chunk combined GEMM on s2
    cudaEventRecord(evConv, 0);
    cudaStreamWaitEvent(s2, evConv, 0);
    {
        int r0 = 0, mrows = 2047;          // levels d=0..10
        dim3 grid(GXS / BN, (mrows + BM - 1) / BM);
        h16gemm_tn<<<grid, gblk, SMEM_GEMM, s2>>>(
            feat16 + (size_t)r0 * FEAT_DIM, w_cat, gx_p + (size_t)r0 * GXS,
            mrows, GXS, FEAT_DIM);
        cudaEventRecord(evChunk[0], s2);
        for (int d = 11; d < DEPTH; d++) {
            r0 = (1 << d) - 1; mrows = 1 << d;
            dim3 g2(GXS / BN, (mrows + BM - 1) / BM);
            h16gemm_tn<<<g2, gblk, SMEM_GEMM, s2>>>(
                feat16 + (size_t)r0 * FEAT_DIM, w_cat, gx_p + (size_t)r0 * GXS,
                mrows, GXS, FEAT_DIM);
            cudaEventRecord(evChunk[d - 10], s2);
        }
    }

    // Recurrence on main stream
    for (int d = 0; d < DEPTH; d++) {
        int n = 1 << d;
        int start = n - 1;
        if (d > 0) {
            int Md = n >> 1;
            int startPrev = Md - 1;
            if (Md <= 256) {
                const float* Aprev = out + (size_t)startPrev * H_DIM;
                dim3 grid(GATE5 / 16, Md);
                small_gemm_tn<<<grid, 256>>>(Aprev, iofuh_w, hh_p, GATE5, FEAT_DIM);
            } else {
                const __half* Aprev = h16 + (size_t)startPrev * H_DIM;
                dim3 grid(GATE5 / BN, (Md + BM - 1) / BM);
                h16gemm_tn<<<grid, gblk, SMEM_GEMM>>>(Aprev, w_iofuh, hh_p, Md, GATE5, FEAT_DIM);
            }
        }
        int ci = (d <= 10) ? 0 : d - 10;
        cudaStreamWaitEvent(0, evChunk[ci], 0);

        int total = n * (H_DIM / 4);
        int nb = (total + 255) / 256;
        int writeH16 = (d >= 9 && d <= 15) ? 1 : 0;
        lstm_level_kernel<<<nb, blk>>>(iofux_b, iofuh_b, px_b, out,
                                       start, n, d > 0 ? 1 : 0, writeH16);
    }
}

// round 16
// speedup vs baseline: 1.1242x; 1.1242x over previous
#include <cuda_runtime.h>
#include <cuda_fp16.h>
#include <math.h>
#include <stdint.h>

// Problem constants
#define FEAT_DIM 512
#define H_DIM    512
#define DEPTH    17
#define N_NODES  ((1 << DEPTH) - 1)   // 131071
#define GATE5    (5 * H_DIM)          // 2560
#define GXS      3072                 // combined row stride: 2560 iofu r + 512 px
#define MAX_PREV (1 << (DEPTH - 2))   // 32768

// ---------------------------------------------------------------------------
// Scratch (static __device__ allocations)
// ---------------------------------------------------------------------------
__device__ __half g_gx   [(size_t)N_NODES * GXS];      // 805 MB combined iofux|px
__device__ float  g_c    [(size_t)N_NODES * H_DIM];    // 268 MB (fp32 recurrence)
__device__ __half g_hh   [(size_t)MAX_PREV * GATE5];   // 168 MB
__device__ __half g_feat16[(size_t)N_NODES * FEAT_DIM];// 134 MB
__device__ __half g_h16   [(size_t)N_NODES * H_DIM];   // 134 MB
__device__ __half g_w_cat [GXS * FEAT_DIM];            // rows 0..2559 iofux, 2560..3071 px
__device__ __half g_w_iofuh[GATE5 * H_DIM];

__device__ __forceinline__ uint32_t smem_u32(const void* p) {
    uint32_t a;
    asm("{ .reg .u64 t; cvta.to.shared.u64 t, %1; cvt.u32.u64 %0, t; }" : "=r"(a) : "l"(p));
    return a;
}
__device__ __forceinline__ uint32_t pack2h(float lo, float hi) {
    __half2 h = __floats2half2_rn(lo, hi);
    return *(uint32_t*)&h;
}

// ---------------------------------------------------------------------------
// fp32 -> fp16 conversion, 4 float4 per thread
// ---------------------------------------------------------------------------
__global__ void __launch_bounds__(256) f2h_kernel(
    const float* __restrict__ in, __half* __restrict__ out, int n4)
{
    int i0 = blockIdx.x * 1024 + threadIdx.x;
#pragma unroll
    for (int u = 0; u < 4; u++) {
        int i = i0 + u * 256;
        if (i < n4) {
            float4 v = ((const float4*)in)[i];
            ((uint2*)out)[i] = make_uint2(pack2h(v.x, v.y), pack2h(v.z, v.w));
        }
    }
}

// ---------------------------------------------------------------------------
// fp16-in fp16-out mma GEMM (R13-validated): cp.async 4-stage ring, one
// barrier per stage. C[M,N] = A[M,K] @ B[N,K]^T. Block 128x128, 256 thr,
// 8 warps (4x2), warp tile 32x64 (2x8 m16n8k16), fp32 accum.
// ---------------------------------------------------------------------------
#define BM 128
#define BN 128
#define BK 32
#define LH 40
#define BUF_B (BM * LH * 2)            // 10240
#define STAGE_B (2 * BUF_B)            // 20480
#define NSTAGE 4
#define SMEM_GEMM (NSTAGE * STAGE_B)   // 81920

__device__ __forceinline__ void mma_f16(float c[4],
                                        uint32_t a0, uint32_t a1, uint32_t a2, uint32_t a3,
                                        uint32_t b0, uint32_t b1)
{
    asm volatile(
        "mma.sync.aligned.m16n8k16.row.col.f32.f16.f16.f32 "
        "{%0,%1,%2,%3}, {%4,%5,%6,%7}, {%8,%9}, {%0,%1,%2,%3};\n"
        : "+f"(c[0]), "+f"(c[1]), "+f"(c[2]), "+f"(c[3])
        : "r"(a0), "r"(a1), "r"(a2), "r"(a3), "r"(b0), "r"(b1));
}
#define LDSM_X4(r0, r1, r2, r3, addr) \
    asm volatile("ldmatrix.sync.aligned.m8n8.x4.shared.b16 {%0,%1,%2,%3}, [%4];" \
                 : "=r"(r0), "=r"(r1), "=r"(r2), "=r"(r3) : "r"(addr))
#define CP_ASYNC16(dst, src) \
    asm volatile("cp.async.cg.shared.global [%0], [%1], 16;" :: "r"(dst), "l"(src) : "memory")
#define CP_COMMIT() asm volatile("cp.async.commit_group;" ::: "memory")
#define CP_WAIT2()  asm volatile("cp.async.wait_group 2;" ::: "memory")

__global__ void __launch_bounds__(256, 2) h16gemm_tn(
    const __half* __restrict__ A, const __half* __restrict__ B,
    __half* __restrict__ C, int M, int N, int K)
{
    extern __shared__ __align__(16) char sm[];
    const uint32_t sb = smem_u32(sm);

    const int tid  = threadIdx.x;
    const int lane = tid & 31;
    const int wid  = tid >> 5;
    const int wm   = wid & 3;
    const int wn   = wid >> 2;
    const int gid  = lane >> 2;
    const int tig  = lane & 3;
    const int bm   = blockIdx.y * BM;
    const int bn   = blockIdx.x * BN;

    const int lrow = tid >> 1;
    const int loff = (tid & 1) * 32;

    int ar = bm + lrow; if (ar >= M) ar = M - 1;
    const char* ApB = (const char*)(A + (size_t)ar * K) + loff;
    const char* BpB = (const char*)(B + (size_t)(bn + lrow) * K) + loff;
    const uint32_t dstA = sb + lrow * 80 + loff;
    const uint32_t dstB = sb + BUF_B + lrow * 80 + loff;

    uint32_t aAdr[2];
#pragma unroll
    for (int mt = 0; mt < 2; mt++) {
        int m0 = wm * 32 + mt * 16;
        aAdr[mt] = sb + (((m0 + (lane & 15)) * LH) + (lane >> 4) * 8) * 2;
    }
    uint32_t bAdr[4];
#pragma unroll
    for (int p = 0; p < 4; p++) {
        int n0 = wn * 64 + p * 16 + ((lane >> 4) << 3) + (lane & 7);
        bAdr[p] = sb + BUF_B + (n0 * LH + (lane & 8)) * 2;
    }

    float acc[2][8][4];
#pragma unroll
    for (int mt = 0; mt < 2; mt++)
#pragma unroll
        for (int nt = 0; nt < 8; nt++)
#pragma unroll
            for (int r = 0; r < 4; r++) acc[mt][nt][r] = 0.f;

    auto issue = [&](int s) {
        const uint32_t so = (uint32_t)(s % NSTAGE) * STAGE_B;
        const int kb = s * BK * 2;
        CP_ASYNC16(dstA + so,      ApB + kb);
        CP_ASYNC16(dstA + so + 16, ApB + kb + 16);
        CP_ASYNC16(dstB + so,      BpB + kb);
        CP_ASYNC16(dstB + so + 16, BpB + kb + 16);
        CP_COMMIT();
    };

    const int nst = K / BK;
    issue(0);
    issue(1);

    for (int s = 0; s < nst; s++) {
        // Writer buffer (s+2)%4; concurrent readers at stage s-1 -> (s-1)%4. Disjoint.
        if (s + 2 < nst) issue(s + 2);
        else             CP_COMMIT();
        CP_WAIT2();
        __syncthreads();

        const uint32_t so = (uint32_t)(s % NSTAGE) * STAGE_B;
#pragma unroll
        for (int ks = 0; ks < 2; ks++) {
            const uint32_t ko = so + ks * 32;
            uint32_t af[2][4];
#pragma unroll
            for (int mt = 0; mt < 2; mt++)
                LDSM_X4(af[mt][0], af[mt][1], af[mt][2], af[mt][3], aAdr[mt] + ko);
            uint32_t bf[8][2];
#pragma unroll
            for (int p = 0; p < 4; p++)
                LDSM_X4(bf[2*p][0], bf[2*p][1], bf[2*p+1][0], bf[2*p+1][1], bAdr[p] + ko);
#pragma unroll
            for (int mt = 0; mt < 2; mt++)
#pragma unroll
                for (int nt = 0; nt < 8; nt++)
                    mma_f16(acc[mt][nt], af[mt][0], af[mt][1], af[mt][2], af[mt][3],
                            bf[nt][0], bf[nt][1]);
        }
    }

#pragma unroll
    for (int mt = 0; mt < 2; mt++) {
        int r0 = bm + wm * 32 + mt * 16 + gid;
        int r1 = r0 + 8;
#pragma unroll
        for (int nt = 0; nt < 8; nt++) {
            int col = bn + wn * 64 + nt * 8 + tig * 2;
            if (r0 < M)
                *(__half2*)(C + (size_t)r0 * N + col) = __floats2half2_rn(acc[mt][nt][0], acc[mt][nt][1]);
            if (r1 < M)
                *(__half2*)(C + (size_t)r1 * N + col) = __floats2half2_rn(acc[mt][nt][2], acc[mt][nt][3]);
        }
    }
}

// ---------------------------------------------------------------------------
// Small-M fp32 GEMM (fp16 out): 16 cols/block x 16 lanes/col, shfl reduce.
// ---------------------------------------------------------------------------
__global__ void __launch_bounds__(256) small_gemm_tn(
    const float* __restrict__ A, const float* __restrict__ B,
    __half* __restrict__ C, int N, int K)
{
    __shared__ float Arow[FEAT_DIM];
    const int tid  = threadIdx.x;
    const int lane = tid & 31;
    const int wid  = tid >> 5;
    const int m    = blockIdx.y;

    if (tid < FEAT_DIM / 4)
        ((float4*)Arow)[tid] = ((const float4*)(A + (size_t)m * K))[tid];
    __syncthreads();

    const int col = blockIdx.x * 16 + wid * 2 + (lane >> 4);
    const int hl  = lane & 15;

    const float4* Br = (const float4*)(B + (size_t)col * K) + hl;
    const float4* Ar = (const float4*)Arow + hl;
    float s = 0.f;
#pragma unroll
    for (int i = 0; i < 8; i++) {
        float4 b = Br[i * 16];
        float4 a = Ar[i * 16];
        s += a.x * b.x + a.y * b.y + a.z * b.z + a.w * b.w;
    }
#pragma unroll
    for (int off = 8; off >= 1; off >>= 1)
        s += __shfl_xor_sync(0xffffffff, s, off);
    if (hl == 0)
        C[(size_t)m * N + col] = __float2half_rn(s);
}

// ---------------------------------------------------------------------------
// Per-level fused gates: combined gx (iofu r | px) fp16 in, fp32 out.
// writeC: skip dead g_c store at the last level; writeH16: only d in [9,15].
// ---------------------------------------------------------------------------
__device__ __forceinline__ float sigf(float x) { return 1.f / (1.f + expf(-x)); }
__device__ __forceinline__ float4 f4add(float4 a, float4 b) {
    return make_float4(a.x + b.x, a.y + b.y, a.z + b.z, a.w + b.w);
}
__device__ __forceinline__ float4 loadh4(const __half* p) {
    __half2 a = *(const __half2*)p;
    __half2 b = *(const __half2*)(p + 2);
    float2 fa = __half22float2(a), fb = __half22float2(b);
    return make_float4(fa.x, fa.y, fb.x, fb.y);
}

__global__ void __launch_bounds__(256) lstm_level_kernel(
    const float* __restrict__ iofux_b, const float* __restrict__ iofuh_b,
    const float* __restrict__ px_b, float* __restrict__ out,
    int start, int n, int hasPrev, int writeH16, int writeC)
{
    int idx = blockIdx.x * 256 + threadIdx.x;
    int total = n * (H_DIM / 4);
    if (idx >= total) return;

    int j  = idx >> 7;
    int t4 = idx & 127;
    size_t g = (size_t)start + j;

    const __half* gx = g_gx + g * GXS + t4 * 4;
    float4 vi = loadh4(gx);
    float4 vo = loadh4(gx + 512);
    float4 vf = loadh4(gx + 1024);
    float4 vu = loadh4(gx + 1536);
    float4 vr = loadh4(gx + 2048);

    float4 pc = make_float4(0.f, 0.f, 0.f, 0.f);
    if (hasPrev) {
        const __half* gh = g_hh + (size_t)(j >> 1) * GATE5 + t4 * 4;
        vi = f4add(vi, loadh4(gh));
        vo = f4add(vo, loadh4(gh + 512));
        vf = f4add(vf, loadh4(gh + 1024));
        vu = f4add(vu, loadh4(gh + 1536));
        vr = f4add(vr, loadh4(gh + 2048));
        size_t parent = (g - 1) >> 1;
        pc = ((const float4*)g_c)[parent * 128 + t4];
    }

    const float4* bx = (const float4*)iofux_b;
    const float4* bh = (const float4*)iofuh_b;
    vi = f4add(vi, f4add(bx[t4],       bh[t4]));
    vo = f4add(vo, f4add(bx[128 + t4], bh[128 + t4]));
    vf = f4add(vf, f4add(bx[256 + t4], bh[256 + t4]));
    vu = f4add(vu, f4add(bx[384 + t4], bh[384 + t4]));
    vr = f4add(vr, f4add(bx[512 + t4], bh[512 + t4]));

    float4 px4 = f4add(loadh4(gx + 2560), ((const float4*)px_b)[t4]);

    float4 c4, h4;
#define GATE(C) {                                                     \
        float i_ = sigf(vi.C); float o_ = sigf(vo.C);                 \
        float f_ = sigf(vf.C); float u_ = tanhf(vu.C);                \
        float r_ = sigf(vr.C);                                        \
        float c_ = i_ * u_ + f_ * pc.C;                               \
        float h_ = o_ * tanhf(c_);                                    \
        c4.C = c_; h4.C = r_ * h_ + (1.f - r_) * px4.C; }
    GATE(x) GATE(y) GATE(z) GATE(w)
#undef GATE

    if (writeC)
        ((float4*)g_c)[g * 128 + t4] = c4;
    ((float4*)out)[g * 128 + t4] = h4;
    if (writeH16)
        *(uint2*)(g_h16 + g * H_DIM + t4 * 4) =
            make_uint2(pack2h(h4.x, h4.y), pack2h(h4.z, h4.w));
}

// ---------------------------------------------------------------------------
// kernel_launch: conversions -> fork (per-level GEMM chunks on s2) -> join
// ---------------------------------------------------------------------------
extern "C" void kernel_launch(void* const* d_in, const int* in_sizes, int n_in,
                              void* d_out, int out_size)
{
    const float* features = (const float*)d_in[0];
    const float* px_w     = (const float*)d_in[1];
    const float* px_b     = (const float*)d_in[2];
    const float* iofux_w  = (const float*)d_in[3];
    const float* iofux_b  = (const float*)d_in[4];
    const float* iofuh_w  = (const float*)d_in[5];
    const float* iofuh_b  = (const float*)d_in[6];
    float* out = (float*)d_out;

    __half *gx_p, *hh_p, *feat16, *h16, *w_cat, *w_iofuh;
    cudaGetSymbolAddress((void**)&gx_p,    g_gx);
    cudaGetSymbolAddress((void**)&hh_p,    g_hh);
    cudaGetSymbolAddress((void**)&feat16,  g_feat16);
    cudaGetSymbolAddress((void**)&h16,     g_h16);
    cudaGetSymbolAddress((void**)&w_cat,   g_w_cat);
    cudaGetSymbolAddress((void**)&w_iofuh, g_w_iofuh);

    static cudaStream_t s2 = nullptr;
    static cudaEvent_t evConv = nullptr;
    static cudaEvent_t evChunk[7];
    if (!s2) {
        cudaStreamCreateWithFlags(&s2, cudaStreamNonBlocking);
        cudaEventCreateWithFlags(&evConv, cudaEventDisableTiming);
        for (int i = 0; i < 7; i++)
            cudaEventCreateWithFlags(&evChunk[i], cudaEventDisableTiming);
        cudaFuncSetAttribute(h16gemm_tn, cudaFuncAttributeMaxDynamicSharedMemorySize, SMEM_GEMM);
    }

    dim3 blk(256);

    // Conversions needed by the fork: features + combined weights
    {
        int n4 = (N_NODES * FEAT_DIM) / 4;
        f2h_kernel<<<(n4 + 1023) / 1024, blk>>>(features, feat16, n4);
        n4 = (GATE5 * FEAT_DIM) / 4;
        f2h_kernel<<<(n4 + 1023) / 1024, blk>>>(iofux_w, w_cat, n4);
        n4 = (H_DIM * FEAT_DIM) / 4;
        f2h_kernel<<<(n4 + 1023) / 1024, blk>>>(px_w, w_cat + (size_t)GATE5 * FEAT_DIM, n4);
    }

    // Fork: per-level-chunk combined GEMM on s2
    cudaEventRecord(evConv, 0);
    cudaStreamWaitEvent(s2, evConv, 0);
    {
        int r0 = 0, mrows = 2047;          // levels d=0..10
        dim3 grid(GXS / BN, (mrows + BM - 1) / BM);
        h16gemm_tn<<<grid, blk, SMEM_GEMM, s2>>>(
            feat16 + (size_t)r0 * FEAT_DIM, w_cat, gx_p + (size_t)r0 * GXS,
            mrows, GXS, FEAT_DIM);
        cudaEventRecord(evChunk[0], s2);
        for (int d = 11; d < DEPTH; d++) {
            r0 = (1 << d) - 1; mrows = 1 << d;
            dim3 g2(GXS / BN, (mrows + BM - 1) / BM);
            h16gemm_tn<<<g2, blk, SMEM_GEMM, s2>>>(
                feat16 + (size_t)r0 * FEAT_DIM, w_cat, gx_p + (size_t)r0 * GXS,
                mrows, GXS, FEAT_DIM);
            cudaEventRecord(evChunk[d - 10], s2);
        }
    }

    // w_iofuh conversion (needed from d=10) overlaps with chunk 0 on s2
    {
        int n4 = (GATE5 * H_DIM) / 4;
        f2h_kernel<<<(n4 + 1023) / 1024, blk>>>(iofuh_w, w_iofuh, n4);
    }

    // Recurrence on main stream
    for (int d = 0; d < DEPTH; d++) {
        int n = 1 << d;
        int start = n - 1;
        if (d > 0) {
            int Md = n >> 1;
            int startPrev = Md - 1;
            if (Md <= 256) {
                const float* Aprev = out + (size_t)startPrev * H_DIM;
                dim3 grid(GATE5 / 16, Md);
                small_gemm_tn<<<grid, 256>>>(Aprev, iofuh_w, hh_p, GATE5, FEAT_DIM);
            } else {
                const __half* Aprev = h16 + (size_t)startPrev * H_DIM;
                dim3 grid(GATE5 / BN, (Md + BM - 1) / BM);
                h16gemm_tn<<<grid, blk, SMEM_GEMM>>>(Aprev, w_iofuh, hh_p, Md, GATE5, FEAT_DIM);
            }
        }
        int ci = (d <= 10) ? 0 : d - 10;
        cudaStreamWaitEvent(0, evChunk[ci], 0);

        int total = n * (H_DIM / 4);
        int nb = (total + 255) / 256;
        int writeH16 = (d >= 9 && d <= 15) ? 1 : 0;
        int writeC   = (d < DEPTH - 1) ? 1 : 0;
        lstm_level_kernel<<<nb, blk>>>(iofux_b, iofuh_b, px_b, out,
                                       start, n, d > 0 ? 1 : 0, writeH16, writeC);
    }
}

// round 17
// speedup vs baseline: 1.1655x; 1.0368x over previous
#include <cuda_runtime.h>
#include <cuda_fp16.h>
#include <math.h>
#include <stdint.h>

// Problem constants
#define FEAT_DIM 512
#define H_DIM    512
#define DEPTH    17
#define N_NODES  ((1 << DEPTH) - 1)   // 131071
#define GATE5    (5 * H_DIM)          // 2560
#define GXS      3072                 // combined row stride: 2560 iofu r + 512 px
#define MAX_PREV (1 << (DEPTH - 2))   // 32768
#define FEAT_SPLIT 32767              // rows for levels d<=14 (conversion half 1)

// ---------------------------------------------------------------------------
// Scratch (static __device__ allocations)
// ---------------------------------------------------------------------------
__device__ __half g_gx   [(size_t)N_NODES * GXS];      // 805 MB combined iofux|px
__device__ float  g_c    [(size_t)N_NODES * H_DIM];    // 268 MB (fp32 recurrence)
__device__ __half g_hh   [(size_t)MAX_PREV * GATE5];   // 168 MB
__device__ __half g_feat16[(size_t)N_NODES * FEAT_DIM];// 134 MB
__device__ __half g_h16   [(size_t)N_NODES * H_DIM];   // 134 MB
__device__ __half g_w_cat [GXS * FEAT_DIM];            // rows 0..2559 iofux, 2560..3071 px
__device__ __half g_w_iofuh[GATE5 * H_DIM];

__device__ __forceinline__ uint32_t smem_u32(const void* p) {
    uint32_t a;
    asm("{ .reg .u64 t; cvta.to.shared.u64 t, %1; cvt.u32.u64 %0, t; }" : "=r"(a) : "l"(p));
    return a;
}
__device__ __forceinline__ uint32_t pack2h(float lo, float hi) {
    __half2 h = __floats2half2_rn(lo, hi);
    return *(uint32_t*)&h;
}

// ---------------------------------------------------------------------------
// fp32 -> fp16 conversion, 4 float4 per thread
// ---------------------------------------------------------------------------
__global__ void __launch_bounds__(256) f2h_kernel(
    const float* __restrict__ in, __half* __restrict__ out, int n4)
{
    int i0 = blockIdx.x * 1024 + threadIdx.x;
#pragma unroll
    for (int u = 0; u < 4; u++) {
        int i = i0 + u * 256;
        if (i < n4) {
            float4 v = ((const float4*)in)[i];
            ((uint2*)out)[i] = make_uint2(pack2h(v.x, v.y), pack2h(v.z, v.w));
        }
    }
}

// ---------------------------------------------------------------------------
// fp16-in fp16-out mma GEMM: cp.async 5-stage ring, issue 3 ahead, one
// barrier per stage. C[M,N] = A[M,K] @ B[N,K]^T. Block 128x128, 256 thr,
// 8 warps (4x2), warp tile 32x64 (2x8 m16n8k16), fp32 accum.
// Ring hazard: writer buf (s+3)%5; laggard readers at stage s-1 use (s-1)%5;
// diff 4 mod 5 != 0 -> disjoint. wait_group 3 guarantees stage s landed.
// ---------------------------------------------------------------------------
#define BM 128
#define BN 128
#define BK 32
#define LH 40
#define BUF_B (BM * LH * 2)            // 10240
#define STAGE_B (2 * BUF_B)            // 20480
#define NSTAGE 5
#define SMEM_GEMM (NSTAGE * STAGE_B)   // 102400

__device__ __forceinline__ void mma_f16(float c[4],
                                        uint32_t a0, uint32_t a1, uint32_t a2, uint32_t a3,
                                        uint32_t b0, uint32_t b1)
{
    asm volatile(
        "mma.sync.aligned.m16n8k16.row.col.f32.f16.f16.f32 "
        "{%0,%1,%2,%3}, {%4,%5,%6,%7}, {%8,%9}, {%0,%1,%2,%3};\n"
        : "+f"(c[0]), "+f"(c[1]), "+f"(c[2]), "+f"(c[3])
        : "r"(a0), "r"(a1), "r"(a2), "r"(a3), "r"(b0), "r"(b1));
}
#define LDSM_X4(r0, r1, r2, r3, addr) \
    asm volatile("ldmatrix.sync.aligned.m8n8.x4.shared.b16 {%0,%1,%2,%3}, [%4];" \
                 : "=r"(r0), "=r"(r1), "=r"(r2), "=r"(r3) : "r"(addr))
#define CP_ASYNC16(dst, src) \
    asm volatile("cp.async.cg.shared.global [%0], [%1], 16;" :: "r"(dst), "l"(src) : "memory")
#define CP_COMMIT() asm volatile("cp.async.commit_group;" ::: "memory")
#define CP_WAIT3()  asm volatile("cp.async.wait_group 3;" ::: "memory")

__global__ void __launch_bounds__(256, 2) h16gemm_tn(
    const __half* __restrict__ A, const __half* __restrict__ B,
    __half* __restrict__ C, int M, int N, int K)
{
    extern __shared__ __align__(16) char sm[];
    const uint32_t sb = smem_u32(sm);

    const int tid  = threadIdx.x;
    const int lane = tid & 31;
    const int wid  = tid >> 5;
    const int wm   = wid & 3;
    const int wn   = wid >> 2;
    const int gid  = lane >> 2;
    const int tig  = lane & 3;
    const int bm   = blockIdx.y * BM;
    const int bn   = blockIdx.x * BN;

    const int lrow = tid >> 1;
    const int loff = (tid & 1) * 32;

    int ar = bm + lrow; if (ar >= M) ar = M - 1;
    const char* ApB = (const char*)(A + (size_t)ar * K) + loff;
    const char* BpB = (const char*)(B + (size_t)(bn + lrow) * K) + loff;
    const uint32_t dstA = sb + lrow * 80 + loff;
    const uint32_t dstB = sb + BUF_B + lrow * 80 + loff;

    uint32_t aAdr[2];
#pragma unroll
    for (int mt = 0; mt < 2; mt++) {
        int m0 = wm * 32 + mt * 16;
        aAdr[mt] = sb + (((m0 + (lane & 15)) * LH) + (lane >> 4) * 8) * 2;
    }
    uint32_t bAdr[4];
#pragma unroll
    for (int p = 0; p < 4; p++) {
        int n0 = wn * 64 + p * 16 + ((lane >> 4) << 3) + (lane & 7);
        bAdr[p] = sb + BUF_B + (n0 * LH + (lane & 8)) * 2;
    }

    float acc[2][8][4];
#pragma unroll
    for (int mt = 0; mt < 2; mt++)
#pragma unroll
        for (int nt = 0; nt < 8; nt++)
#pragma unroll
            for (int r = 0; r < 4; r++) acc[mt][nt][r] = 0.f;

    auto issue = [&](int s) {
        const uint32_t so = (uint32_t)(s % NSTAGE) * STAGE_B;
        const int kb = s * BK * 2;
        CP_ASYNC16(dstA + so,      ApB + kb);
        CP_ASYNC16(dstA + so + 16, ApB + kb + 16);
        CP_ASYNC16(dstB + so,      BpB + kb);
        CP_ASYNC16(dstB + so + 16, BpB + kb + 16);
        CP_COMMIT();
    };

    const int nst = K / BK;
    issue(0);
    issue(1);
    issue(2);

    for (int s = 0; s < nst; s++) {
        if (s + 3 < nst) issue(s + 3);
        else             CP_COMMIT();
        CP_WAIT3();
        __syncthreads();

        const uint32_t so = (uint32_t)(s % NSTAGE) * STAGE_B;
#pragma unroll
        for (int ks = 0; ks < 2; ks++) {
            const uint32_t ko = so + ks * 32;
            uint32_t af[2][4];
#pragma unroll
            for (int mt = 0; mt < 2; mt++)
                LDSM_X4(af[mt][0], af[mt][1], af[mt][2], af[mt][3], aAdr[mt] + ko);
            uint32_t bf[8][2];
#pragma unroll
            for (int p = 0; p < 4; p++)
                LDSM_X4(bf[2*p][0], bf[2*p][1], bf[2*p+1][0], bf[2*p+1][1], bAdr[p] + ko);
#pragma unroll
            for (int mt = 0; mt < 2; mt++)
#pragma unroll
                for (int nt = 0; nt < 8; nt++)
                    mma_f16(acc[mt][nt], af[mt][0], af[mt][1], af[mt][2], af[mt][3],
                            bf[nt][0], bf[nt][1]);
        }
    }

#pragma unroll
    for (int mt = 0; mt < 2; mt++) {
        int r0 = bm + wm * 32 + mt * 16 + gid;
        int r1 = r0 + 8;
#pragma unroll
        for (int nt = 0; nt < 8; nt++) {
            int col = bn + wn * 64 + nt * 8 + tig * 2;
            if (r0 < M)
                *(__half2*)(C + (size_t)r0 * N + col) = __floats2half2_rn(acc[mt][nt][0], acc[mt][nt][1]);
            if (r1 < M)
                *(__half2*)(C + (size_t)r1 * N + col) = __floats2half2_rn(acc[mt][nt][2], acc[mt][nt][3]);
        }
    }
}

// ---------------------------------------------------------------------------
// Small-M fp32 GEMM (fp16 out): 16 cols/block x 16 lanes/col, shfl reduce.
// ---------------------------------------------------------------------------
__global__ void __launch_bounds__(256) small_gemm_tn(
    const float* __restrict__ A, const float* __restrict__ B,
    __half* __restrict__ C, int N, int K)
{
    __shared__ float Arow[FEAT_DIM];
    const int tid  = threadIdx.x;
    const int lane = tid & 31;
    const int wid  = tid >> 5;
    const int m    = blockIdx.y;

    if (tid < FEAT_DIM / 4)
        ((float4*)Arow)[tid] = ((const float4*)(A + (size_t)m * K))[tid];
    __syncthreads();

    const int col = blockIdx.x * 16 + wid * 2 + (lane >> 4);
    const int hl  = lane & 15;

    const float4* Br = (const float4*)(B + (size_t)col * K) + hl;
    const float4* Ar = (const float4*)Arow + hl;
    float s = 0.f;
#pragma unroll
    for (int i = 0; i < 8; i++) {
        float4 b = Br[i * 16];
        float4 a = Ar[i * 16];
        s += a.x * b.x + a.y * b.y + a.z * b.z + a.w * b.w;
    }
#pragma unroll
    for (int off = 8; off >= 1; off >>= 1)
        s += __shfl_xor_sync(0xffffffff, s, off);
    if (hl == 0)
        C[(size_t)m * N + col] = __float2half_rn(s);
}

// ---------------------------------------------------------------------------
// Per-level fused gates: combined gx (iofu r | px) fp16 in, fp32 out.
// writeC: skip dead g_c store at last level; writeH16: only d in [9,15].
// ---------------------------------------------------------------------------
__device__ __forceinline__ float sigf(float x) { return 1.f / (1.f + expf(-x)); }
__device__ __forceinline__ float4 f4add(float4 a, float4 b) {
    return make_float4(a.x + b.x, a.y + b.y, a.z + b.z, a.w + b.w);
}
__device__ __forceinline__ float4 loadh4(const __half* p) {
    __half2 a = *(const __half2*)p;
    __half2 b = *(const __half2*)(p + 2);
    float2 fa = __half22float2(a), fb = __half22float2(b);
    return make_float4(fa.x, fa.y, fb.x, fb.y);
}

__global__ void __launch_bounds__(256) lstm_level_kernel(
    const float* __restrict__ iofux_b, const float* __restrict__ iofuh_b,
    const float* __restrict__ px_b, float* __restrict__ out,
    int start, int n, int hasPrev, int writeH16, int writeC)
{
    int idx = blockIdx.x * 256 + threadIdx.x;
    int total = n * (H_DIM / 4);
    if (idx >= total) return;

    int j  = idx >> 7;
    int t4 = idx & 127;
    size_t g = (size_t)start + j;

    const __half* gx = g_gx + g * GXS + t4 * 4;
    float4 vi = loadh4(gx);
    float4 vo = loadh4(gx + 512);
    float4 vf = loadh4(gx + 1024);
    float4 vu = loadh4(gx + 1536);
    float4 vr = loadh4(gx + 2048);

    float4 pc = make_float4(0.f, 0.f, 0.f, 0.f);
    if (hasPrev) {
        const __half* gh = g_hh + (size_t)(j >> 1) * GATE5 + t4 * 4;
        vi = f4add(vi, loadh4(gh));
        vo = f4add(vo, loadh4(gh + 512));
        vf = f4add(vf, loadh4(gh + 1024));
        vu = f4add(vu, loadh4(gh + 1536));
        vr = f4add(vr, loadh4(gh + 2048));
        size_t parent = (g - 1) >> 1;
        pc = ((const float4*)g_c)[parent * 128 + t4];
    }

    const float4* bx = (const float4*)iofux_b;
    const float4* bh = (const float4*)iofuh_b;
    vi = f4add(vi, f4add(bx[t4],       bh[t4]));
    vo = f4add(vo, f4add(bx[128 + t4], bh[128 + t4]));
    vf = f4add(vf, f4add(bx[256 + t4], bh[256 + t4]));
    vu = f4add(vu, f4add(bx[384 + t4], bh[384 + t4]));
    vr = f4add(vr, f4add(bx[512 + t4], bh[512 + t4]));

    float4 px4 = f4add(loadh4(gx + 2560), ((const float4*)px_b)[t4]);

    float4 c4, h4;
#define GATE(C) {                                                     \
        float i_ = sigf(vi.C); float o_ = sigf(vo.C);                 \
        float f_ = sigf(vf.C); float u_ = tanhf(vu.C);                \
        float r_ = sigf(vr.C);                                        \
        float c_ = i_ * u_ + f_ * pc.C;                               \
        float h_ = o_ * tanhf(c_);                                    \
        c4.C = c_; h4.C = r_ * h_ + (1.f - r_) * px4.C; }
    GATE(x) GATE(y) GATE(z) GATE(w)
#undef GATE

    if (writeC)
        ((float4*)g_c)[g * 128 + t4] = c4;
    ((float4*)out)[g * 128 + t4] = h4;
    if (writeH16)
        *(uint2*)(g_h16 + g * H_DIM + t4 * 4) =
            make_uint2(pack2h(h4.x, h4.y), pack2h(h4.z, h4.w));
}

// ---------------------------------------------------------------------------
// kernel_launch: split conversions -> fork (per-level GEMM chunks on s2)
// ---------------------------------------------------------------------------
extern "C" void kernel_launch(void* const* d_in, const int* in_sizes, int n_in,
                              void* d_out, int out_size)
{
    const float* features = (const float*)d_in[0];
    const float* px_w     = (const float*)d_in[1];
    const float* px_b     = (const float*)d_in[2];
    const float* iofux_w  = (const float*)d_in[3];
    const float* iofux_b  = (const float*)d_in[4];
    const float* iofuh_w  = (const float*)d_in[5];
    const float* iofuh_b  = (const float*)d_in[6];
    float* out = (float*)d_out;

    __half *gx_p, *hh_p, *feat16, *h16, *w_cat, *w_iofuh;
    cudaGetSymbolAddress((void**)&gx_p,    g_gx);
    cudaGetSymbolAddress((void**)&hh_p,    g_hh);
    cudaGetSymbolAddress((void**)&feat16,  g_feat16);
    cudaGetSymbolAddress((void**)&h16,     g_h16);
    cudaGetSymbolAddress((void**)&w_cat,   g_w_cat);
    cudaGetSymbolAddress((void**)&w_iofuh, g_w_iofuh);

    static cudaStream_t s2 = nullptr;
    static cudaEvent_t evConv1 = nullptr, evConv2 = nullptr;
    static cudaEvent_t evChunk[7];
    if (!s2) {
        cudaStreamCreateWithFlags(&s2, cudaStreamNonBlocking);
        cudaEventCreateWithFlags(&evConv1, cudaEventDisableTiming);
        cudaEventCreateWithFlags(&evConv2, cudaEventDisableTiming);
        for (int i = 0; i < 7; i++)
            cudaEventCreateWithFlags(&evChunk[i], cudaEventDisableTiming);
        cudaFuncSetAttribute(h16gemm_tn, cudaFuncAttributeMaxDynamicSharedMemorySize, SMEM_GEMM);
    }

    dim3 blk(256);

    // Conversion half 1: feature rows for levels d<=14, plus combined weights
    {
        int n4 = (FEAT_SPLIT * FEAT_DIM) / 4;
        f2h_kernel<<<(n4 + 1023) / 1024, blk>>>(features, feat16, n4);
        n4 = (GATE5 * FEAT_DIM) / 4;
        f2h_kernel<<<(n4 + 1023) / 1024, blk>>>(iofux_w, w_cat, n4);
        n4 = (H_DIM * FEAT_DIM) / 4;
        f2h_kernel<<<(n4 + 1023) / 1024, blk>>>(px_w, w_cat + (size_t)GATE5 * FEAT_DIM, n4);
    }
    cudaEventRecord(evConv1, 0);
    cudaStreamWaitEvent(s2, evConv1, 0);

    // s2: chunks for levels d<=14 (ci 0..4)
    {
        int r0 = 0, mrows = 2047;          // levels d=0..10
        dim3 grid(GXS / BN, (mrows + BM - 1) / BM);
        h16gemm_tn<<<grid, blk, SMEM_GEMM, s2>>>(
            feat16 + (size_t)r0 * FEAT_DIM, w_cat, gx_p + (size_t)r0 * GXS,
            mrows, GXS, FEAT_DIM);
        cudaEventRecord(evChunk[0], s2);
        for (int d = 11; d <= 14; d++) {
            r0 = (1 << d) - 1; mrows = 1 << d;
            dim3 g2(GXS / BN, (mrows + BM - 1) / BM);
            h16gemm_tn<<<g2, blk, SMEM_GEMM, s2>>>(
                feat16 + (size_t)r0 * FEAT_DIM, w_cat, gx_p + (size_t)r0 * GXS,
                mrows, GXS, FEAT_DIM);
            cudaEventRecord(evChunk[d - 10], s2);
        }
    }

    // Conversion half 2 (feature rows for d=15,16) overlaps chunk 0..4 GEMMs
    {
        size_t off4 = (size_t)FEAT_SPLIT * FEAT_DIM / 4;
        int n4 = (int)(((size_t)N_NODES * FEAT_DIM) / 4 - off4);
        f2h_kernel<<<(n4 + 1023) / 1024, blk>>>(features + off4 * 4,
                                                feat16 + off4 * 4, n4);
    }
    cudaEventRecord(evConv2, 0);
    cudaStreamWaitEvent(s2, evConv2, 0);

    // s2: chunks d=15,16
    for (int d = 15; d < DEPTH; d++) {
        int r0 = (1 << d) - 1, mrows = 1 << d;
        dim3 g2(GXS / BN, (mrows + BM - 1) / BM);
        h16gemm_tn<<<g2, blk, SMEM_GEMM, s2>>>(
            feat16 + (size_t)r0 * FEAT_DIM, w_cat, gx_p + (size_t)r0 * GXS,
            mrows, GXS, FEAT_DIM);
        cudaEventRecord(evChunk[d - 10], s2);
    }

    // w_iofuh conversion (needed from d=10) overlaps chunk GEMMs
    {
        int n4 = (GATE5 * H_DIM) / 4;
        f2h_kernel<<<(n4 + 1023) / 1024, blk>>>(iofuh_w, w_iofuh, n4);
    }

    // Recurrence on main stream
    for (int d = 0; d < DEPTH; d++) {
        int n = 1 << d;
        int start = n - 1;
        if (d > 0) {
            int Md = n >> 1;
            int startPrev = Md - 1;
            if (Md <= 256) {
                const float* Aprev = out + (size_t)startPrev * H_DIM;
                dim3 grid(GATE5 / 16, Md);
                small_gemm_tn<<<grid, 256>>>(Aprev, iofuh_w, hh_p, GATE5, FEAT_DIM);
            } else {
                const __half* Aprev = h16 + (size_t)startPrev * H_DIM;
                dim3 grid(GATE5 / BN, (Md + BM - 1) / BM);
                h16gemm_tn<<<grid, blk, SMEM_GEMM>>>(Aprev, w_iofuh, hh_p, Md, GATE5, FEAT_DIM);
            }
        }
        int ci = (d <= 10) ? 0 : d - 10;
        cudaStreamWaitEvent(0, evChunk[ci], 0);

        int total = n * (H_DIM / 4);
        int nb = (total + 255) / 256;
        int writeH16 = (d >= 9 && d <= 15) ? 1 : 0;
        int writeC   = (d < DEPTH - 1) ? 1 : 0;
        lstm_level_kernel<<<nb, blk>>>(iofux_b, iofuh_b, px_b, out,
                                       start, n, d > 0 ? 1 : 0, writeH16, writeC);
    }
}